// round 4
// baseline (speedup 1.0000x reference)
#include <cuda_runtime.h>
#include <cuda_bf16.h>
#include <math.h>

// 8192*8192 winner table: packed = ((pair_idx+1) << 3) | bucket, 0 = untouched.
// Zero-initialized at module load; the winner in se_write_kernel resets its
// cell to 0 on every call, so each graph replay sees a zeroed table again.
#define N_CELLS (64u * 1024u * 1024u)
__device__ int g_scratch[N_CELLS];

#define UNROLL 4

// Election: fire-and-forget atomicMax (REDG.MAX) into g_scratch.
// Runs CONCURRENTLY with the d_out memset (disjoint buffers, forked stream).
__global__ void se_elect_kernel(const int* __restrict__ src,
                                const int* __restrict__ dst,
                                const int* __restrict__ path_len,
                                int n_pairs, int nn, int max_path) {
    int base = blockIdx.x * (blockDim.x * UNROLL) + threadIdx.x;
#pragma unroll
    for (int k = 0; k < UNROLL; k++) {
        int i = base + k * blockDim.x;
        if (i < n_pairs) {
            int pl = path_len[i];
            int bu = (pl < max_path ? pl : max_path) - 1;
            if (bu < 0) bu = 0;
            int packed = ((i + 1) << 3) | bu;
            unsigned cell = (unsigned)src[i] * (unsigned)nn + (unsigned)dst[i];
            atomicMax(&g_scratch[cell], packed);
        }
    }
}

// Winner writes its bias value, resets its scratch cell (self-clean for the
// next replay). Exactly one winner per touched cell -> race-free stores.
// Losers reading a reset cell see 0 != their packed -> still losers.
// Batched UNROLL pairs/thread: independent random loads issued back-to-back
// for MLP before any dependent use.
__global__ void se_write_kernel(const float* __restrict__ b,
                                const int* __restrict__ src,
                                const int* __restrict__ dst,
                                const int* __restrict__ path_len,
                                int n_pairs, int nn, int max_path,
                                float* __restrict__ out_f) {
    int base = blockIdx.x * (blockDim.x * UNROLL) + threadIdx.x;

    unsigned cell[UNROLL];
    int packed[UNROLL];
    int bu[UNROLL];
    int w[UNROLL];
    bool valid[UNROLL];

#pragma unroll
    for (int k = 0; k < UNROLL; k++) {
        int i = base + k * blockDim.x;
        valid[k] = (i < n_pairs);
        if (valid[k]) {
            int pl = path_len[i];
            int t = (pl < max_path ? pl : max_path) - 1;
            bu[k] = t < 0 ? 0 : t;
            packed[k] = ((i + 1) << 3) | bu[k];
            cell[k] = (unsigned)src[i] * (unsigned)nn + (unsigned)dst[i];
        }
    }
    // issue all random scratch reads (independent -> overlapped latency)
#pragma unroll
    for (int k = 0; k < UNROLL; k++) {
        if (valid[k]) w[k] = g_scratch[cell[k]];
    }
#pragma unroll
    for (int k = 0; k < UNROLL; k++) {
        if (valid[k] && w[k] == packed[k]) {
            out_f[cell[k]] = __ldg(&b[bu[k]]);
            g_scratch[cell[k]] = 0;   // self-clean for next replay
        }
    }
}

extern "C" void kernel_launch(void* const* d_in, const int* in_sizes, int n_in,
                              void* d_out, int out_size) {
    // inputs: x [n_nodes,128] f32 (unused), b [max_path] f32,
    //         src [n_pairs] i32, dst [n_pairs] i32, path_len [n_pairs] i32
    const float* b        = (const float*)d_in[1];
    const int*   src      = (const int*)d_in[2];
    const int*   dst      = (const int*)d_in[3];
    const int*   path_len = (const int*)d_in[4];

    int max_path = in_sizes[1];
    int n_pairs  = in_sizes[2];
    int nn = (int)(sqrt((double)out_size) + 0.5);

    float* out_f = (float*)d_out;

    // One-time side-stream + events for the capture fork (no device allocs).
    static cudaStream_t s2 = nullptr;
    static cudaEvent_t evFork = nullptr, evJoin = nullptr;
    if (s2 == nullptr) {
        cudaStreamCreateWithFlags(&s2, cudaStreamNonBlocking);
        cudaEventCreateWithFlags(&evFork, cudaEventDisableTiming);
        cudaEventCreateWithFlags(&evJoin, cudaEventDisableTiming);
    }

    const int T = 256;
    int pair_blocks = (n_pairs + T * UNROLL - 1) / (T * UNROLL);

    // Fork: elect (g_scratch) runs concurrently with the d_out memset.
    cudaEventRecord(evFork, 0);
    cudaStreamWaitEvent(s2, evFork, 0);

    se_elect_kernel<<<pair_blocks, T, 0, s2>>>(src, dst, path_len,
                                               n_pairs, nn, max_path);

    cudaMemsetAsync(d_out, 0, (size_t)out_size * sizeof(float), 0);

    // Join: write pass depends on BOTH memset (stream 0) and elect (s2).
    cudaEventRecord(evJoin, s2);
    cudaStreamWaitEvent(0, evJoin, 0);

    se_write_kernel<<<pair_blocks, T>>>(b, src, dst, path_len,
                                        n_pairs, nn, max_path, out_f);
}